// round 1
// baseline (speedup 1.0000x reference)
#include <cuda_runtime.h>
#include <cuda_bf16.h>

// Closed-form per-(batch,class) reduction of the symmetric-pair loss.
// For a group of n points of one symmetric class (c in {0,1,2}), with
// u_i = x_i - CENTER_X:
//   sum_{i<j} (u_i+u_j)^2       = (n-2)*Sum(u^2) + (Sum u)^2
//   sum_{i<j} (y_i-y_j)^2       =  n   *Sum(y^2) - (Sum y)^2
//   #pairs                      =  n(n-1)/2
// Both loss identities are exactly 0 for n=0 and n=1, so no special cases.

#define CENTER_X 0.5f
#define BATCH 256
#define NPTS  512

__device__ double g_partial[2 * BATCH];  // (loss, count) per batch

__global__ void __launch_bounds__(256) sym_per_batch(const float* __restrict__ kp,
                                                     const int* __restrict__ cls) {
    const int b = blockIdx.x;
    const int t = threadIdx.x;

    const float2* p2 = reinterpret_cast<const float2*>(kp) + (size_t)b * NPTS;
    const int*    cb = cls + (size_t)b * NPTS;

    float su[3], su2[3], sy[3], sy2[3];
    int cnt[3];
#pragma unroll
    for (int k = 0; k < 3; k++) { su[k] = su2[k] = sy[k] = sy2[k] = 0.0f; cnt[k] = 0; }

#pragma unroll
    for (int r = 0; r < NPTS / 256; r++) {
        const int i = t + r * 256;
        const float2 p = p2[i];
        const int c = cb[i];
        const float u = p.x - CENTER_X;
#pragma unroll
        for (int k = 0; k < 3; k++) {
            if (c == k) {
                su[k]  += u;
                su2[k] += u * u;
                sy[k]  += p.y;
                sy2[k] += p.y * p.y;
                cnt[k] += 1;
            }
        }
    }

    // Intra-warp reduction (shuffles)
#pragma unroll
    for (int off = 16; off > 0; off >>= 1) {
#pragma unroll
        for (int k = 0; k < 3; k++) {
            su[k]  += __shfl_down_sync(0xffffffffu, su[k],  off);
            su2[k] += __shfl_down_sync(0xffffffffu, su2[k], off);
            sy[k]  += __shfl_down_sync(0xffffffffu, sy[k],  off);
            sy2[k] += __shfl_down_sync(0xffffffffu, sy2[k], off);
            cnt[k] += __shfl_down_sync(0xffffffffu, cnt[k], off);
        }
    }

    // Cross-warp via shared memory (8 warps)
    __shared__ float sf[8][12];
    __shared__ int   si[8][3];
    const int wid = t >> 5, lid = t & 31;
    if (lid == 0) {
#pragma unroll
        for (int k = 0; k < 3; k++) {
            sf[wid][k * 4 + 0] = su[k];
            sf[wid][k * 4 + 1] = su2[k];
            sf[wid][k * 4 + 2] = sy[k];
            sf[wid][k * 4 + 3] = sy2[k];
            si[wid][k]         = cnt[k];
        }
    }
    __syncthreads();

    if (t == 0) {
        double loss = 0.0, count = 0.0;
#pragma unroll
        for (int k = 0; k < 3; k++) {
            double SU = 0.0, SU2 = 0.0, SY = 0.0, SY2 = 0.0, n = 0.0;
#pragma unroll
            for (int w = 0; w < 8; w++) {
                SU  += (double)sf[w][k * 4 + 0];
                SU2 += (double)sf[w][k * 4 + 1];
                SY  += (double)sf[w][k * 4 + 2];
                SY2 += (double)sf[w][k * 4 + 3];
                n   += (double)si[w][k];
            }
            loss  += (n - 2.0) * SU2 + SU * SU + n * SY2 - SY * SY;
            count += n * (n - 1.0) * 0.5;
        }
        g_partial[2 * b + 0] = loss;
        g_partial[2 * b + 1] = count;
    }
}

__global__ void __launch_bounds__(256) sym_finalize(float* __restrict__ out) {
    __shared__ double sl[256], sc[256];
    const int t = threadIdx.x;
    sl[t] = g_partial[2 * t + 0];
    sc[t] = g_partial[2 * t + 1];
    __syncthreads();
#pragma unroll
    for (int off = 128; off > 0; off >>= 1) {
        if (t < off) { sl[t] += sl[t + off]; sc[t] += sc[t + off]; }
        __syncthreads();
    }
    if (t == 0) {
        const double cnt = sc[0] < 1.0 ? 1.0 : sc[0];
        out[0] = (float)(sl[0] / cnt);
    }
}

extern "C" void kernel_launch(void* const* d_in, const int* in_sizes, int n_in,
                              void* d_out, int out_size) {
    const float* kp  = (const float*)d_in[0];  // [256, 512, 2] f32
    const int*   cls = (const int*)d_in[1];    // [256, 512] i32
    float* out = (float*)d_out;

    sym_per_batch<<<BATCH, 256>>>(kp, cls);
    sym_finalize<<<1, 256>>>(out);
}